// round 17
// baseline (speedup 1.0000x reference)
#include <cuda_runtime.h>
#include <cuda_fp16.h>
#include <cstdint>

// ---- lc_kernel smem layout (32-bit words) ----
#define USLOTW 16384            // one u slot: 16l * 32k * 128B = 64KB
#define WSM_OFF 32768           // after 2 u slots
#define WQS 552                 // w q-stride (bank-bijective with frag loads)
#define WLS 34                  // w l-stride (32 o + 2 pad)
#define WBUFW 8832              // 16 q * 552 (one w slot, 32 k)
#define KOFF_OFF 50432          // after 2 w slots
#define SEP_BS 34
#define SEP_PS 2176             // 64 * 34
#define SMEM_BYTES (51008 * 4)  // 204,032 B

__device__ __align__(256) __half g_xh[64 * 34 * 34 * 64];  // [c][hp][wp][b] fp16

__device__ __forceinline__ uint32_t f16x2(float hi, float lo) {
    uint32_t d; asm("cvt.rn.f16x2.f32 %0,%1,%2;" : "=r"(d) : "f"(hi), "f"(lo)); return d;
}
__device__ __forceinline__ uint32_t s2u(const void* p) {
    uint32_t a;
    asm("{.reg .u64 t; cvta.to.shared.u64 t,%1; cvt.u32.u64 %0,t;}" : "=r"(a) : "l"(p));
    return a;
}
#define MMAF16(d, a, b) asm volatile( \
    "mma.sync.aligned.m16n8k16.row.col.f32.f16.f16.f32 " \
    "{%0,%1,%2,%3},{%4,%5,%6,%7},{%8,%9},{%0,%1,%2,%3};" \
    : "+f"((d)[0]), "+f"((d)[1]), "+f"((d)[2]), "+f"((d)[3]) \
    : "r"((a)[0]), "r"((a)[1]), "r"((a)[2]), "r"((a)[3]), "r"((b)[0]), "r"((b)[1]))

// ---------------------------------------------------------------------------
__global__ void prep_kernel(const float* __restrict__ x) {
    int tid = threadIdx.x;
    if (blockIdx.x >= 2048) {
        int idx = (blockIdx.x - 2048) * 256 + tid;     // 64c * 132 cells * 8
        if (idx >= 64 * 132 * 8) return;
        int g8 = idx & 7, r = idx >> 3;
        int c = r / 132, cell = r % 132;
        int hp, wp;
        if (cell < 34)       { hp = 0;  wp = cell; }
        else if (cell < 68)  { hp = 33; wp = cell - 34; }
        else if (cell < 100) { hp = cell - 68 + 1;  wp = 0; }
        else                 { hp = cell - 100 + 1; wp = 33; }
        *(uint4*)&g_xh[((c * 34 + hp) * 34 + wp) * 64 + g8 * 8] = make_uint4(0, 0, 0, 0);
        return;
    }
    __shared__ float t[32][65];
    int c = blockIdx.x & 63, h = blockIdx.x >> 6;
    int w = tid & 31, b0 = tid >> 5;
#pragma unroll
    for (int p = 0; p < 8; p++)
        t[w][b0 * 8 + p] = x[(((b0 * 8 + p) * 64 + c) * 32 + h) * 32 + w];
    __syncthreads();
    int b = tid & 63, wq = tid >> 6;
#pragma unroll
    for (int p = 0; p < 8; p++) {
        int ww = wq * 8 + p;
        g_xh[((c * 34 + h + 1) * 34 + ww + 1) * 64 + b] = __float2half_rn(t[ww][b]);
    }
}

// ---------------------------------------------------------------------------
// lc_kernel: 128 CTAs = 64 l-tiles x 2 o-halves. CTA = 16 l x 32 o x 64 b.
// 512 threads = 16 warps; warp = pixel, tile M64(b) x N32(o), k-chunk 32.
// u: cp.async (2 slots, issued post-barrier) -> swizzled [l][k][b] -> ldmatrix.
// w: LDG f32 -> cvt f16x2 at load (two 8-reg stages) -> STS (2 slots).
// ---------------------------------------------------------------------------
__global__ __launch_bounds__(512, 1)
void lc_kernel(const float* __restrict__ weight, const float* __restrict__ bias,
               float* __restrict__ out) {
    extern __shared__ uint32_t sm[];
    uint32_t* wsm = sm + WSM_OFF;
    int* koff = (int*)(sm + KOFF_OFF);
    const uint32_t sbase = s2u(sm);

    const int tid = threadIdx.x, lane = tid & 31, pix = tid >> 5;
    const int l_tile = blockIdx.x >> 1, o0 = (blockIdx.x & 1) << 5;
    const int l0 = l_tile << 4;
    const int h = l0 >> 5, w0 = l0 & 31;            // 16-aligned tile: single h
    const int cq = lane & 3, rr = lane >> 2;

    for (int k = tid; k < 576; k += 512) {
        int c = k / 9, r = k - 9 * c, i = r / 3, j = r - 3 * i;
        koff[k] = (c * 1156 + i * 34 + j) * 64;     // half-element units
    }

    // ---- u cp.async mapping: us8 = tid&7, uk = (tid>>3)&15, ul = tid>>7 ----
    const int us8 = tid & 7, uk = (tid >> 3) & 15, ul = tid >> 7;  // ul 0..3
    const __half* usrc0 = g_xh + (h * 34 + w0 + ul) * 64 + us8 * 8;
    const uint32_t udst0 = sbase +
        (uint32_t)(ul * 4096 + uk * 128 + ((us8 ^ (uk & 7)) << 4));

    // ---- w fill: w_q0 = tid>>7 (0..3), o = (tid>>2)&31, lq = tid&3 ----
    const int w_q0 = tid >> 7, w_o = (tid >> 2) & 31, w_lq = tid & 3;
    const float* wsrc = weight + (size_t)(o0 + w_o) * 576 * 1024 + l0 + w_lq * 4;

    // ---- ldmatrix lane mapping ----
    const int kr = (lane & 7) | ((lane & 16) >> 1);  // k-row 0..15 within half
    const int bh = (lane >> 3) & 1;                  // b half
    const int k7 = kr & 7;

    uint32_t wsA[8], wsB[8];
    auto issue_u = [&](int ch, int slot) {
        int ko0 = koff[ch * 32 + uk];
        int ko1 = koff[ch * 32 + 16 + uk];
        uint32_t d = udst0 + (uint32_t)slot * 65536u;
#pragma unroll
        for (int i = 0; i < 4; i++) {
            asm volatile("cp.async.cg.shared.global [%0],[%1],16;"
                         :: "r"(d + (uint32_t)i * 16384u), "l"(usrc0 + i * 256 + ko0));
            asm volatile("cp.async.cg.shared.global [%0],[%1],16;"
                         :: "r"(d + (uint32_t)i * 16384u + 2048u), "l"(usrc0 + i * 256 + ko1));
        }
        asm volatile("cp.async.commit_group;" ::: "memory");
    };
    auto ldg_half = [&](int ch, int kh, uint32_t* ws) {
        int kb = ch * 32 + kh * 16 + 2 * w_q0;
        const float* s0 = wsrc + (size_t)kb * 1024;
        float4 a0 = *(const float4*)s0;
        float4 a1 = *(const float4*)(s0 + 1024);
        float4 b0 = *(const float4*)(s0 + 8 * 1024);
        float4 b1 = *(const float4*)(s0 + 9 * 1024);
        ws[0] = f16x2(a1.x, a0.x); ws[1] = f16x2(a1.y, a0.y);
        ws[2] = f16x2(a1.z, a0.z); ws[3] = f16x2(a1.w, a0.w);
        ws[4] = f16x2(b1.x, b0.x); ws[5] = f16x2(b1.y, b0.y);
        ws[6] = f16x2(b1.z, b0.z); ws[7] = f16x2(b1.w, b0.w);
    };
    auto sts_half = [&](int slot, int kh, const uint32_t* ws) {
        uint32_t* d0 = wsm + slot * WBUFW + (kh * 8 + w_q0) * WQS + (w_lq * 4) * WLS + w_o;
#pragma unroll
        for (int s2 = 0; s2 < 2; s2++) {
            uint32_t* d = d0 + s2 * 4 * WQS;
            d[0 * WLS] = ws[s2 * 4 + 0];
            d[1 * WLS] = ws[s2 * 4 + 1];
            d[2 * WLS] = ws[s2 * 4 + 2];
            d[3 * WLS] = ws[s2 * 4 + 3];
        }
    };

    float acc[16][4];
#pragma unroll
    for (int i = 0; i < 16; i++)
#pragma unroll
        for (int j = 0; j < 4; j++) acc[i][j] = 0.f;

    __syncthreads();                      // koff ready
    issue_u(0, 0);
    ldg_half(0, 0, wsA);
    ldg_half(0, 1, wsB);

    for (int ch = 0; ch < 18; ch++) {
        const int s = ch & 1;
        sts_half(s, 0, wsA);
        if (ch < 17) ldg_half(ch + 1, 0, wsA);
        sts_half(s, 1, wsB);
        if (ch < 17) ldg_half(ch + 1, 1, wsB);
        asm volatile("cp.async.wait_group 0;" ::: "memory");   // u(ch) complete
        __syncthreads();
        if (ch < 17) issue_u(ch + 1, s ^ 1);                   // post-barrier: safe

#pragma unroll
        for (int kh = 0; kh < 2; kh++) {
            const uint32_t* B = wsm + s * WBUFW + (kh * 8 + cq) * WQS + pix * WLS + rr;
            uint32_t bfr[4][2];
#pragma unroll
            for (int nt = 0; nt < 4; nt++) {
                bfr[nt][0] = B[nt * 8];
                bfr[nt][1] = B[4 * WQS + nt * 8];
            }
            const uint32_t abase = sbase + (uint32_t)s * 65536u +
                (uint32_t)(pix * 4096 + (kh * 16 + kr) * 128);
#pragma unroll
            for (int mt = 0; mt < 4; mt++) {
                uint32_t a[4];
                uint32_t ad = abase + (uint32_t)((((2 * mt + bh) ^ k7) << 4));
                asm volatile("ldmatrix.sync.aligned.m8n8.x4.trans.shared.b16 "
                             "{%0,%1,%2,%3},[%4];"
                             : "=r"(a[0]), "=r"(a[1]), "=r"(a[2]), "=r"(a[3]) : "r"(ad));
#pragma unroll
                for (int nt = 0; nt < 4; nt++)
                    MMAF16(acc[mt * 4 + nt], a, bfr[nt]);
            }
        }
    }
    __syncthreads();

    // ---- epilogue: sep[pix][b][o] staging, then 64B coalesced rows ----
    float* sep = (float*)sm;
#pragma unroll
    for (int mt = 0; mt < 4; mt++)
#pragma unroll
        for (int nt = 0; nt < 4; nt++) {
            const float* d = acc[mt * 4 + nt];
            int b = mt * 16 + rr, o = nt * 8 + 2 * cq;
            float* pp = sep + pix * SEP_PS + b * SEP_BS + o;
            *(float2*)pp                = make_float2(d[0], d[1]);
            *(float2*)(pp + 8 * SEP_BS) = make_float2(d[2], d[3]);
        }
    __syncthreads();
#pragma unroll
    for (int it = 0; it < 4; it++) {
        int unit = tid + (it << 9);
        int o = unit & 31, b = unit >> 5;
        float v[16];
#pragma unroll
        for (int l = 0; l < 16; l++) v[l] = sep[l * SEP_PS + b * SEP_BS + o];
        const float* bp = bias + (size_t)(o0 + o) * 1024 + l0;
        float* dp = out + ((size_t)(b * 64 + o0 + o)) * 1024 + l0;
#pragma unroll
        for (int g = 0; g < 4; g++) {
            float4 bv = *(const float4*)(bp + 4 * g);
            *(float4*)(dp + 4 * g) = make_float4(v[4 * g] + bv.x, v[4 * g + 1] + bv.y,
                                                 v[4 * g + 2] + bv.z, v[4 * g + 3] + bv.w);
        }
    }
}

// ---------------------------------------------------------------------------
extern "C" void kernel_launch(void* const* d_in, const int* in_sizes, int n_in,
                              void* d_out, int out_size) {
    const float* x      = (const float*)d_in[0];
    const float* weight = (const float*)d_in[1];
    const float* bias   = (const float*)d_in[2];
    float* out = (float*)d_out;

    cudaFuncSetAttribute(lc_kernel, cudaFuncAttributeMaxDynamicSharedMemorySize, SMEM_BYTES);

    prep_kernel<<<2048 + 264, 256>>>(x);
    lc_kernel<<<128, 512, SMEM_BYTES>>>(weight, bias, out);
}